// round 1
// baseline (speedup 1.0000x reference)
#include <cuda_runtime.h>
#include <math.h>

#define LNUM 4
#define BB   64
#define NNODE 511
#define SS   512
#define DD   256
#define HH   8
#define HDIM 32
#define DFFN 512
#define MTOK (BB*SS)          /* 32768 */

typedef unsigned long long ull;

/* ------------------------------------------------------------------ */
/* Scratch (device globals; no allocations allowed)                    */
/* ------------------------------------------------------------------ */
__device__ float g_x  [(size_t)MTOK*DD];        /* residual stream */
__device__ float g_h  [(size_t)MTOK*DD];        /* layernorm out   */
__device__ float g_qkv[(size_t)MTOK*3*DD];      /* qkv             */
__device__ float g_o  [(size_t)MTOK*DD];        /* attn out        */
__device__ float g_ff [(size_t)MTOK*DFFN];      /* ff intermediate */
__device__ unsigned char g_et[(size_t)BB*NNODE*512]; /* edge types, rows padded to 512 */

/* ------------------------------------------------------------------ */
/* packed f32x2 helpers (sm_103a FFMA2 path)                           */
/* ------------------------------------------------------------------ */
__device__ __forceinline__ ull pk2(float lo, float hi) {
    ull r; asm("mov.b64 %0, {%1,%2};" : "=l"(r) : "f"(lo), "f"(hi)); return r;
}
__device__ __forceinline__ float2 upk2(ull v) {
    float2 f; asm("mov.b64 {%0,%1}, %2;" : "=f"(f.x), "=f"(f.y) : "l"(v)); return f;
}
__device__ __forceinline__ ull ffma2(ull a, ull b, ull c) {
    ull d; asm("fma.rn.f32x2 %0, %1, %2, %3;" : "=l"(d) : "l"(a), "l"(b), "l"(c)); return d;
}

/* ------------------------------------------------------------------ */
/* embed: x[b,0,:]=game_token; x[b,s,:]=patch_emb[cell_states[b,s-1]]  */
/* ------------------------------------------------------------------ */
__global__ void embed_kernel(const int* __restrict__ cs,
                             const float* __restrict__ patch_emb,
                             const float* __restrict__ game_token) {
    int row = blockIdx.x;            /* 0..32767 */
    int d   = threadIdx.x;           /* 0..255   */
    int b = row >> 9, s = row & 511;
    float v;
    if (s == 0) v = game_token[d];
    else        v = patch_emb[cs[b*NNODE + s - 1]*DD + d];
    g_x[(size_t)row*DD + d] = v;
}

/* compress edge_type_matrix (int32) -> u8 with 512-padded rows */
__global__ void etcomp_kernel(const int* __restrict__ etm) {
    int i = blockIdx.x*blockDim.x + threadIdx.x;
    const int total = BB*NNODE*NNODE;
    if (i >= total) return;
    int b = i / (NNODE*NNODE);
    int r = i - b*(NNODE*NNODE);
    int q = r / NNODE;
    int k = r - q*NNODE;
    g_et[((size_t)(b*NNODE + q))*512 + k] = (unsigned char)etm[i];
}

/* ------------------------------------------------------------------ */
/* layernorm: g_h = LN(g_x) * gamma + beta   (one warp per row)        */
/* ------------------------------------------------------------------ */
__global__ void ln_kernel(const float* __restrict__ gam, const float* __restrict__ bet) {
    int w = threadIdx.x >> 5, lane = threadIdx.x & 31;
    int row = blockIdx.x*8 + w;
    const float* xr = g_x + (size_t)row*DD;
    float4 v0 = *(const float4*)(xr + lane*8);
    float4 v1 = *(const float4*)(xr + lane*8 + 4);
    float s = v0.x+v0.y+v0.z+v0.w + v1.x+v1.y+v1.z+v1.w;
    float q = v0.x*v0.x+v0.y*v0.y+v0.z*v0.z+v0.w*v0.w
            + v1.x*v1.x+v1.y*v1.y+v1.z*v1.z+v1.w*v1.w;
#pragma unroll
    for (int o = 16; o; o >>= 1) {
        s += __shfl_xor_sync(0xffffffffu, s, o);
        q += __shfl_xor_sync(0xffffffffu, q, o);
    }
    float m   = s * (1.f/256.f);
    float var = q * (1.f/256.f) - m*m;
    float rs  = rsqrtf(var + 1e-5f);
    int d = lane*8;
    float4 ga = *(const float4*)(gam + d);
    float4 gb = *(const float4*)(gam + d + 4);
    float4 ba = *(const float4*)(bet + d);
    float4 bb = *(const float4*)(bet + d + 4);
    float4 o0, o1;
    o0.x = (v0.x-m)*rs*ga.x + ba.x;  o0.y = (v0.y-m)*rs*ga.y + ba.y;
    o0.z = (v0.z-m)*rs*ga.z + ba.z;  o0.w = (v0.w-m)*rs*ga.w + ba.w;
    o1.x = (v1.x-m)*rs*gb.x + bb.x;  o1.y = (v1.y-m)*rs*gb.y + bb.y;
    o1.z = (v1.z-m)*rs*gb.z + bb.z;  o1.w = (v1.w-m)*rs*gb.w + bb.w;
    float* hr = g_h + (size_t)row*DD;
    *(float4*)(hr + lane*8)     = o0;
    *(float4*)(hr + lane*8 + 4) = o1;
}

/* ------------------------------------------------------------------ */
/* SGEMM: C[M,Nn] (+)= A[M,K] @ W[Nn,K]^T + bias                       */
/* VAR: 0 plain, 1 relu, 2 residual-add into C                        */
/* tiles: 128x64x16, 256 thr, thread tile 8x4, FFMA2 pairs-over-rows  */
/* ------------------------------------------------------------------ */
template<int VAR>
__global__ void __launch_bounds__(256)
gemm_kernel(const float* __restrict__ A, const float* __restrict__ W,
            const float* __restrict__ bias, float* __restrict__ C,
            int Nn, int K) {
    __shared__ float As[16][132];
    __shared__ float Bs[16][68];
    const int t  = threadIdx.x;
    const int tr = t >> 4;            /* 0..15 -> rows tr*8..tr*8+7   */
    const int tc = t & 15;            /* 0..15 -> cols tc*4..tc*4+3   */
    const int m0 = blockIdx.y * 128;
    const int n0 = blockIdx.x * 64;
    const int lr  = t >> 2;           /* 0..63 */
    const int lc4 = (t & 3) * 4;      /* 0,4,8,12 */

    ull acc[4][4];
#pragma unroll
    for (int i = 0; i < 4; ++i)
#pragma unroll
        for (int j = 0; j < 4; ++j) acc[i][j] = pk2(0.f, 0.f);

    for (int k0 = 0; k0 < K; k0 += 16) {
        float4 a0 = *(const float4*)(A + (size_t)(m0+lr   )*K + k0 + lc4);
        float4 a1 = *(const float4*)(A + (size_t)(m0+lr+64)*K + k0 + lc4);
        float4 b0 = *(const float4*)(W + (size_t)(n0+lr   )*K + k0 + lc4);
        __syncthreads();
        As[lc4+0][lr]    = a0.x; As[lc4+1][lr]    = a0.y;
        As[lc4+2][lr]    = a0.z; As[lc4+3][lr]    = a0.w;
        As[lc4+0][lr+64] = a1.x; As[lc4+1][lr+64] = a1.y;
        As[lc4+2][lr+64] = a1.z; As[lc4+3][lr+64] = a1.w;
        Bs[lc4+0][lr]    = b0.x; Bs[lc4+1][lr]    = b0.y;
        Bs[lc4+2][lr]    = b0.z; Bs[lc4+3][lr]    = b0.w;
        __syncthreads();
#pragma unroll
        for (int kk = 0; kk < 16; ++kk) {
            float4 av0 = *(const float4*)&As[kk][tr*8];
            float4 av1 = *(const float4*)&As[kk][tr*8 + 4];
            float4 bv  = *(const float4*)&Bs[kk][tc*4];
            ull ap0 = pk2(av0.x, av0.y), ap1 = pk2(av0.z, av0.w);
            ull ap2 = pk2(av1.x, av1.y), ap3 = pk2(av1.z, av1.w);
            float bj[4] = {bv.x, bv.y, bv.z, bv.w};
#pragma unroll
            for (int j = 0; j < 4; ++j) {
                ull bd = pk2(bj[j], bj[j]);
                acc[0][j] = ffma2(ap0, bd, acc[0][j]);
                acc[1][j] = ffma2(ap1, bd, acc[1][j]);
                acc[2][j] = ffma2(ap2, bd, acc[2][j]);
                acc[3][j] = ffma2(ap3, bd, acc[3][j]);
            }
        }
    }
#pragma unroll
    for (int rp = 0; rp < 4; ++rp) {
#pragma unroll
        for (int j = 0; j < 4; ++j) {
            float2 f = upk2(acc[rp][j]);
            int n = n0 + tc*4 + j;
            float bsv = bias[n];
            size_t i0 = (size_t)(m0 + tr*8 + rp*2    )*Nn + n;
            size_t i1 = (size_t)(m0 + tr*8 + rp*2 + 1)*Nn + n;
            float v0 = f.x + bsv, v1 = f.y + bsv;
            if (VAR == 1) { v0 = fmaxf(v0, 0.f); v1 = fmaxf(v1, 0.f); }
            if (VAR == 2) { v0 += C[i0]; v1 += C[i1]; }
            C[i0] = v0; C[i1] = v1;
        }
    }
}

/* ------------------------------------------------------------------ */
/* fused attention: one block per (b,h); K,V,attn rows in smem         */
/* ------------------------------------------------------------------ */
#define KS_LD 516
#define ATTN_SMEM_FLOATS (32*KS_LD + 512*32 + 8*2048 + 8*128)
#define ATTN_SMEM_BYTES  (ATTN_SMEM_FLOATS*4)

__global__ void __launch_bounds__(256)
attn_kernel(const float* __restrict__ edge_emb) {
    extern __shared__ float sm[];
    float* Ks   = sm;                       /* [32][516] transposed  */
    float* Vs   = Ks + 32*KS_LD;            /* [512][32]             */
    float* attn = Vs + 512*32;              /* [8][512][4] swizzled  */
    float* qs   = attn + 8*2048;            /* [8][128]              */

    const int bh = blockIdx.x;
    const int b  = bh >> 3, h = bh & 7;
    const int t  = threadIdx.x;
    const int w  = t >> 5, lane = t & 31;

    const float eb0 = edge_emb[0*HH + h];
    const float eb1 = edge_emb[1*HH + h];
    const float eb2 = edge_emb[2*HH + h];

    const float* base = g_qkv + ((size_t)b*SS)*768 + h*HDIM;
    /* fill K (transposed) and V */
    for (int it = 0; it < 64; ++it) {
        int s = it*8 + w;
        Ks[lane*KS_LD + s] = base[(size_t)s*768 + 256 + lane];
        Vs[s*32 + lane]    = base[(size_t)s*768 + 512 + lane];
    }
    __syncthreads();

    float* aw = attn + w*2048;
    float* qw = qs + w*128;
    const float inv = 0.17677669529663687f;   /* 1/sqrt(32) */

    for (int gi = 0; gi < 16; ++gi) {
        const int q0 = (gi*8 + w)*4;
        /* stage q (4 rows) into per-warp smem, layout [d][r] */
#pragma unroll
        for (int r = 0; r < 4; ++r)
            qw[lane*4 + r] = base[(size_t)(q0 + r)*768 + lane];
        __syncwarp();

        ull acc[16][2];
#pragma unroll
        for (int j = 0; j < 16; ++j) { acc[j][0] = pk2(0.f,0.f); acc[j][1] = pk2(0.f,0.f); }

#pragma unroll 4
        for (int d = 0; d < 32; ++d) {
            float4 qv = *(const float4*)&qw[d*4];
            ull qp0 = pk2(qv.x, qv.y), qp1 = pk2(qv.z, qv.w);
            const float* kr = &Ks[d*KS_LD + lane*16];
            float4 k0 = ((const float4*)kr)[0];
            float4 k1 = ((const float4*)kr)[1];
            float4 k2 = ((const float4*)kr)[2];
            float4 k3 = ((const float4*)kr)[3];
            float kvals[16] = {k0.x,k0.y,k0.z,k0.w, k1.x,k1.y,k1.z,k1.w,
                               k2.x,k2.y,k2.z,k2.w, k3.x,k3.y,k3.z,k3.w};
#pragma unroll
            for (int j = 0; j < 16; ++j) {
                ull bd = pk2(kvals[j], kvals[j]);
                acc[j][0] = ffma2(qp0, bd, acc[j][0]);
                acc[j][1] = ffma2(qp1, bd, acc[j][1]);
            }
        }

        /* unpack scores */
        float p[4][16];
#pragma unroll
        for (int j = 0; j < 16; ++j) {
            float2 fa = upk2(acc[j][0]);
            float2 fb = upk2(acc[j][1]);
            p[0][j] = fa.x; p[1][j] = fa.y; p[2][j] = fb.x; p[3][j] = fb.y;
        }

        /* scale + edge bias */
#pragma unroll
        for (int r = 0; r < 4; ++r) {
            int q = q0 + r;
            if (q > 0) {
                const unsigned char* etr = g_et + ((size_t)(b*NNODE + (q-1)))*512;
                uint4 ev = *(const uint4*)(etr + lane*16);
                unsigned int wd[4] = {ev.x, ev.y, ev.z, ev.w};
                unsigned int last = (ev.w >> 24) & 0xffu;
                unsigned int prev = __shfl_up_sync(0xffffffffu, last, 1);
#pragma unroll
                for (int j = 0; j < 16; ++j) {
                    float bi;
                    if (j == 0) {
                        bi = (lane == 0) ? 0.f
                             : (prev == 0u ? eb0 : (prev == 1u ? eb1 : eb2));
                    } else {
                        unsigned int e = (wd[(j-1)>>2] >> (8*((j-1)&3))) & 0xffu;
                        bi = (e == 0u ? eb0 : (e == 1u ? eb1 : eb2));
                    }
                    p[r][j] = p[r][j]*inv + bi;
                }
            } else {
#pragma unroll
                for (int j = 0; j < 16; ++j) p[r][j] *= inv;
            }
        }

        /* softmax per row */
#pragma unroll
        for (int r = 0; r < 4; ++r) {
            float m = -1e30f;
#pragma unroll
            for (int j = 0; j < 16; ++j) m = fmaxf(m, p[r][j]);
#pragma unroll
            for (int o = 16; o; o >>= 1) m = fmaxf(m, __shfl_xor_sync(0xffffffffu, m, o));
            float s = 0.f;
#pragma unroll
            for (int j = 0; j < 16; ++j) { p[r][j] = __expf(p[r][j] - m); s += p[r][j]; }
#pragma unroll
            for (int o = 16; o; o >>= 1) s += __shfl_xor_sync(0xffffffffu, s, o);
            float is = 1.f / s;
#pragma unroll
            for (int j = 0; j < 16; ++j) p[r][j] *= is;
        }

        /* store attn rows (swizzled for conflict-light STS.128) */
#pragma unroll
        for (int j = 0; j < 16; ++j) {
            int key = lane*16 + j;
            int idx = key ^ ((key >> 4) & 7);
            *(float4*)&aw[idx*4] = make_float4(p[0][j], p[1][j], p[2][j], p[3][j]);
        }
        __syncwarp();

        /* o = attn @ V ; lane owns dim d=lane */
        ull o0 = pk2(0.f,0.f), o1 = pk2(0.f,0.f);
#pragma unroll 8
        for (int key = 0; key < 512; ++key) {
            int idx = key ^ ((key >> 4) & 7);
            float4 a4 = *(const float4*)&aw[idx*4];
            float v = Vs[key*32 + lane];
            ull vd = pk2(v, v);
            o0 = ffma2(pk2(a4.x, a4.y), vd, o0);
            o1 = ffma2(pk2(a4.z, a4.w), vd, o1);
        }
        float2 oa = upk2(o0), ob = upk2(o1);
        float* op = g_o + ((size_t)b*SS + q0)*DD + h*HDIM + lane;
        op[0]     = oa.x;
        op[DD]    = oa.y;
        op[2*DD]  = ob.x;
        op[3*DD]  = ob.y;
        __syncwarp();
    }
}

/* ------------------------------------------------------------------ */
/* head: g = x[:,0,:]; o=relu(g@fc1^T+b); policy, value                */
/* ------------------------------------------------------------------ */
__global__ void head_kernel(const float* __restrict__ fc1w, const float* __restrict__ fc1b,
                            const float* __restrict__ polw, const float* __restrict__ polb,
                            const float* __restrict__ valw, const float* __restrict__ valb,
                            float* __restrict__ out) {
    __shared__ float gs[256];
    __shared__ float os[64];
    int b = blockIdx.x, t = threadIdx.x;
    const float* xr = g_x + ((size_t)b*SS)*DD;
#pragma unroll
    for (int i = 0; i < 4; ++i) gs[t + i*64] = xr[t + i*64];
    __syncthreads();
    float a = fc1b[t];
#pragma unroll 8
    for (int k = 0; k < 256; ++k) a += gs[k] * fc1w[t*256 + k];
    os[t] = fmaxf(a, 0.f);
    __syncthreads();
    if (t < 7) {
        float pacc = polb[t];
#pragma unroll
        for (int j = 0; j < 64; ++j) pacc += os[j] * polw[t*64 + j];
        out[b*7 + t] = pacc;
    }
    if (t == 7) {
        float va = valb[0];
#pragma unroll
        for (int j = 0; j < 64; ++j) va += os[j] * valw[j];
        out[BB*7 + b] = tanhf(va);
    }
}

/* ------------------------------------------------------------------ */
extern "C" void kernel_launch(void* const* d_in, const int* in_sizes, int n_in,
                              void* d_out, int out_size) {
    const int*   cs    = (const int*)d_in[0];
    const int*   etm   = (const int*)d_in[1];
    const float* pe    = (const float*)d_in[2];
    const float* gt    = (const float*)d_in[3];
    const float* ee    = (const float*)d_in[4];
    const float* in_w  = (const float*)d_in[5];
    const float* in_b  = (const float*)d_in[6];
    const float* outw  = (const float*)d_in[7];
    const float* outb  = (const float*)d_in[8];
    const float* ff1w  = (const float*)d_in[9];
    const float* ff1b  = (const float*)d_in[10];
    const float* ff2w  = (const float*)d_in[11];
    const float* ff2b  = (const float*)d_in[12];
    const float* ln1g  = (const float*)d_in[13];
    const float* ln1b  = (const float*)d_in[14];
    const float* ln2g  = (const float*)d_in[15];
    const float* ln2b  = (const float*)d_in[16];
    const float* fc1w  = (const float*)d_in[17];
    const float* fc1b  = (const float*)d_in[18];
    const float* polw  = (const float*)d_in[19];
    const float* polb  = (const float*)d_in[20];
    const float* valw  = (const float*)d_in[21];
    const float* valb  = (const float*)d_in[22];
    float* out = (float*)d_out;

    float *px, *ph, *pq, *po, *pf;
    cudaGetSymbolAddress((void**)&px, g_x);
    cudaGetSymbolAddress((void**)&ph, g_h);
    cudaGetSymbolAddress((void**)&pq, g_qkv);
    cudaGetSymbolAddress((void**)&po, g_o);
    cudaGetSymbolAddress((void**)&pf, g_ff);

    cudaFuncSetAttribute(attn_kernel, cudaFuncAttributeMaxDynamicSharedMemorySize,
                         ATTN_SMEM_BYTES);

    embed_kernel<<<MTOK, 256>>>(cs, pe, gt);
    etcomp_kernel<<<(BB*NNODE*NNODE + 255)/256, 256>>>(etm);

    for (int i = 0; i < LNUM; ++i) {
        ln_kernel<<<MTOK/8, 256>>>(ln1g + i*DD, ln1b + i*DD);
        gemm_kernel<0><<<dim3(12, 256), 256>>>(ph, in_w + (size_t)i*768*256,
                                               in_b + i*768, pq, 768, 256);
        attn_kernel<<<BB*HH, 256, ATTN_SMEM_BYTES>>>(ee);
        gemm_kernel<2><<<dim3(4, 256), 256>>>(po, outw + (size_t)i*256*256,
                                              outb + i*256, px, 256, 256);
        ln_kernel<<<MTOK/8, 256>>>(ln2g + i*DD, ln2b + i*DD);
        gemm_kernel<1><<<dim3(8, 256), 256>>>(ph, ff1w + (size_t)i*512*256,
                                              ff1b + i*512, pf, 512, 256);
        gemm_kernel<2><<<dim3(4, 256), 256>>>(pf, ff2w + (size_t)i*256*512,
                                              ff2b + i*256, px, 256, 512);
    }
    head_kernel<<<BB, 64>>>(fc1w, fc1b, polw, polb, valw, valb, out);
}